// round 11
// baseline (speedup 1.0000x reference)
#include <cuda_runtime.h>
#include <cstdint>

#define NPROP   2048
#define MAXN    256
#define D1      64
#define D2      128
#define D3      256
#define MIN_PTS 4
#define EPS     1e-6f
#define CHUNK   128

// ---- smem layout (float offsets) ----
#define OFF_FE   0                          // 256 pooled feats
#define H1TROW   136                        // 128 + 8 pad (conflict-free B-frag reads)
#define H2TROW   136
#define OFF_H1T  256                        // h1 transposed [i=64][pt<=128]   (8704 floats)
#define OFF_H2T  (OFF_H1T + D1 * H1TROW)    // h2 transposed [j=128][pt<=128]  (17408 floats)
#define SMEM_FLOATS (OFF_H2T + D2 * H2TROW) // 26368
#define SMEM_BYTES  (SMEM_FLOATS * 4)       // 105,472 B -> two CTAs per SM

// round fp32 -> nearest tf32-representable value (bits / float)
__device__ __forceinline__ uint32_t f32_to_tf32_bits(float x) {
    uint32_t r;
    asm("cvt.rna.tf32.f32 %0, %1;" : "=r"(r) : "f"(x));
    return r;
}
__device__ __forceinline__ float f32_to_tf32_f(float x) {
    return __uint_as_float(f32_to_tf32_bits(x));
}

// D(16x8) += A(16x8,row) * B(8x8,col), tf32 in, f32 accum (sm_80+ baseline PTX).
#define MMA_TF32(c, a, b) \
    asm volatile("mma.sync.aligned.m16n8k8.row.col.f32.tf32.tf32.f32 " \
        "{%0,%1,%2,%3}, {%4,%5,%6,%7}, {%8,%9}, {%0,%1,%2,%3};" \
        : "+f"((c)[0]), "+f"((c)[1]), "+f"((c)[2]), "+f"((c)[3]) \
        : "r"((a)[0]), "r"((a)[1]), "r"((a)[2]), "r"((a)[3]), \
          "r"((b)[0]), "r"((b)[1]))

__global__ __launch_bounds__(256, 2)
void refine_head_kernel(const float* __restrict__ points,
                        const int*   __restrict__ counts,
                        const float* __restrict__ proposals,
                        const float* __restrict__ W1, const float* __restrict__ b1,
                        const float* __restrict__ W2, const float* __restrict__ b2,
                        const float* __restrict__ W3, const float* __restrict__ b3,
                        const float* __restrict__ Wc, const float* __restrict__ bc,
                        const float* __restrict__ Wr, const float* __restrict__ br,
                        float* __restrict__ out)
{
    extern __shared__ float sm[];
    const int b    = blockIdx.x;
    const int tid  = threadIdx.x;
    const int wid  = tid >> 5;
    const int lane = tid & 31;
    const int tid4 = lane & 3;
    const int gid  = lane >> 2;
    const int n    = counts[b];

    // Invalid proposal: outputs are pure biases (uniform early-out).
    if (n < MIN_PTS) {
        if (tid == 0) out[b] = bc[0];
        if (tid < 6)  out[NPROP + b * 6 + tid] = br[tid];
        return;
    }

    // L3 running max, [mt*2 + rowhalf]; persists across point-chunks.
    float mx[4] = {-3.402823466e38f, -3.402823466e38f,
                   -3.402823466e38f, -3.402823466e38f};

    const int npc = (n + CHUNK - 1) >> 7;   // 1 or 2 point-chunks

    for (int pc = 0; pc < npc; pc++) {
        const int pbase = pc << 7;
        const int cn    = min(CHUNK, n - pbase);
        const int c16   = (cn + 15) >> 4;

        // ---- Phase 0: thread = point in chunk (only the first n unique points
        // matter — the reference's arange(256)%n gather merely duplicates points
        // and max-pool is duplicate-invariant). Layer 1 -> h1t[i][pt], tf32. ----
        if (tid < cn) {
            const float* pp = points + ((long)b * MAXN + pbase + tid) * 3;
            const float* pr = proposals + b * 6;
            const float c0 = (pp[0] - pr[0]) / (fabsf(pr[3]) + EPS);
            const float c1 = (pp[1] - pr[1]) / (fabsf(pr[4]) + EPS);
            const float c2 = (pp[2] - pr[2]) / (fabsf(pr[5]) + EPS);

            #pragma unroll
            for (int q = 0; q < 16; q++) {
                float4 a  = __ldg((const float4*)(W1)       + q);
                float4 d  = __ldg((const float4*)(W1 + 64)  + q);
                float4 e  = __ldg((const float4*)(W1 + 128) + q);
                float4 f  = __ldg((const float4*)(b1)       + q);
                float h0 = fmaxf(fmaf(c0, a.x, fmaf(c1, d.x, fmaf(c2, e.x, f.x))), 0.f);
                float h1v= fmaxf(fmaf(c0, a.y, fmaf(c1, d.y, fmaf(c2, e.y, f.y))), 0.f);
                float h2v= fmaxf(fmaf(c0, a.z, fmaf(c1, d.z, fmaf(c2, e.z, f.z))), 0.f);
                float h3 = fmaxf(fmaf(c0, a.w, fmaf(c1, d.w, fmaf(c2, e.w, f.w))), 0.f);
                sm[OFF_H1T + (q*4+0) * H1TROW + tid] = f32_to_tf32_f(h0);
                sm[OFF_H1T + (q*4+1) * H1TROW + tid] = f32_to_tf32_f(h1v);
                sm[OFF_H1T + (q*4+2) * H1TROW + tid] = f32_to_tf32_f(h2v);
                sm[OFF_H1T + (q*4+3) * H1TROW + tid] = f32_to_tf32_f(h3);
            }
        }
        __syncthreads();

        // ---- Layer 2 on tensor cores: D[ch][pt] = W2T @ h1t. Warp w owns the
        // m16 channel tile [w*16, w*16+16). Output IS the h2t layout L3 reads. ----
        {
            const int chb = wid * 16;

            uint32_t A2[8][4];
            #pragma unroll
            for (int s = 0; s < 8; s++) {
                const int j0 = s * 8 + tid4;
                A2[s][0] = f32_to_tf32_bits(__ldg(W2 + j0 * D2 + chb + gid));
                A2[s][1] = f32_to_tf32_bits(__ldg(W2 + j0 * D2 + chb + gid + 8));
                A2[s][2] = f32_to_tf32_bits(__ldg(W2 + (j0 + 4) * D2 + chb + gid));
                A2[s][3] = f32_to_tf32_bits(__ldg(W2 + (j0 + 4) * D2 + chb + gid + 8));
            }
            const float b2v0 = __ldg(b2 + chb + gid);
            const float b2v1 = __ldg(b2 + chb + gid + 8);

            for (int ck = 0; ck < c16; ck++) {
                const int colb = ck * 16;
                float c2[2][4];
                #pragma unroll
                for (int nt = 0; nt < 2; nt++)
                    #pragma unroll
                    for (int q = 0; q < 4; q++) c2[nt][q] = 0.f;

                #pragma unroll
                for (int s = 0; s < 8; s++) {
                    uint32_t bf[2][2];
                    #pragma unroll
                    for (int nt = 0; nt < 2; nt++) {
                        const int col = colb + nt * 8 + gid;
                        bf[nt][0] = __float_as_uint(
                            sm[OFF_H1T + (s * 8 + tid4) * H1TROW + col]);
                        bf[nt][1] = __float_as_uint(
                            sm[OFF_H1T + (s * 8 + tid4 + 4) * H1TROW + col]);
                    }
                    MMA_TF32(c2[0], A2[s], bf[0]);
                    MMA_TF32(c2[1], A2[s], bf[1]);
                }

                // epilogue: relu + bias, tf32-round, store into h2t
                #pragma unroll
                for (int nt = 0; nt < 2; nt++) {
                    const int col0 = colb + nt * 8 + 2 * tid4;
                    float2 v0, v1;
                    v0.x = f32_to_tf32_f(fmaxf(c2[nt][0] + b2v0, 0.f));
                    v0.y = f32_to_tf32_f(fmaxf(c2[nt][1] + b2v0, 0.f));
                    v1.x = f32_to_tf32_f(fmaxf(c2[nt][2] + b2v1, 0.f));
                    v1.y = f32_to_tf32_f(fmaxf(c2[nt][3] + b2v1, 0.f));
                    *(float2*)&sm[OFF_H2T + (chb + gid)     * H2TROW + col0] = v0;
                    *(float2*)&sm[OFF_H2T + (chb + gid + 8) * H2TROW + col0] = v1;
                }
            }
        }
        __syncthreads();

        // ---- Layer 3 + max-pool on tensor cores. Warp w owns channels
        // [w*32, w*32+32); mt-split keeps only a 64-reg A tile live. ----
        {
            const int chb = wid * 32;

            #pragma unroll
            for (int mt = 0; mt < 2; mt++) {
                const int ch = chb + mt * 16 + gid;
                uint32_t A[16][4];
                #pragma unroll
                for (int s = 0; s < 16; s++) {
                    const int j0 = s * 8 + tid4;
                    A[s][0] = f32_to_tf32_bits(__ldg(W3 + j0 * D3 + ch));
                    A[s][1] = f32_to_tf32_bits(__ldg(W3 + j0 * D3 + ch + 8));
                    A[s][2] = f32_to_tf32_bits(__ldg(W3 + (j0 + 4) * D3 + ch));
                    A[s][3] = f32_to_tf32_bits(__ldg(W3 + (j0 + 4) * D3 + ch + 8));
                }

                for (int ck = 0; ck < c16; ck++) {
                    const int colb = ck * 16;
                    float c[2][4];
                    #pragma unroll
                    for (int nt = 0; nt < 2; nt++)
                        #pragma unroll
                        for (int q = 0; q < 4; q++) c[nt][q] = 0.f;

                    #pragma unroll
                    for (int s = 0; s < 16; s++) {
                        uint32_t bf[2][2];
                        #pragma unroll
                        for (int nt = 0; nt < 2; nt++) {
                            const int col = colb + nt * 8 + gid;
                            bf[nt][0] = __float_as_uint(
                                sm[OFF_H2T + (s * 8 + tid4) * H2TROW + col]);
                            bf[nt][1] = __float_as_uint(
                                sm[OFF_H2T + (s * 8 + tid4 + 4) * H2TROW + col]);
                        }
                        MMA_TF32(c[0], A[s], bf[0]);
                        MMA_TF32(c[1], A[s], bf[1]);
                    }

                    // fold into running per-row max (mask by GLOBAL point index)
                    #pragma unroll
                    for (int nt = 0; nt < 2; nt++) {
                        const int col0 = pbase + colb + nt * 8 + 2 * tid4;
                        if (col0 < n) {
                            mx[mt*2+0] = fmaxf(mx[mt*2+0], c[nt][0]);
                            mx[mt*2+1] = fmaxf(mx[mt*2+1], c[nt][2]);
                        }
                        if (col0 + 1 < n) {
                            mx[mt*2+0] = fmaxf(mx[mt*2+0], c[nt][1]);
                            mx[mt*2+1] = fmaxf(mx[mt*2+1], c[nt][3]);
                        }
                    }
                }
            }
        }
        __syncthreads();   // protect h1t/h2t before next chunk overwrites
    }

    // ---- Pool finish: quad-lane max union, + b3 -> feats in smem ----
    {
        #pragma unroll
        for (int o = 1; o < 4; o <<= 1) {
            #pragma unroll
            for (int q = 0; q < 4; q++)
                mx[q] = fmaxf(mx[q], __shfl_xor_sync(0xffffffffu, mx[q], o));
        }
        if (tid4 == 0) {
            #pragma unroll
            for (int mt = 0; mt < 2; mt++)
                #pragma unroll
                for (int rh = 0; rh < 2; rh++) {
                    const int ch = wid * 32 + mt * 16 + rh * 8 + gid;
                    sm[OFF_FE + ch] = mx[mt*2+rh] + __ldg(b3 + ch);
                }
        }
    }
    __syncthreads();

    // ---- Heads: 7 warps, each one dot(feats, column) + bias ----
    {
        if (wid < 7) {
            float s = 0.f;
            if (wid == 0) {
                #pragma unroll
                for (int k = lane; k < D3; k += 32) s += sm[OFF_FE + k] * __ldg(Wc + k);
            } else {
                const int r = wid - 1;
                #pragma unroll
                for (int k = lane; k < D3; k += 32) s += sm[OFF_FE + k] * __ldg(Wr + k * 6 + r);
            }
            #pragma unroll
            for (int off = 16; off > 0; off >>= 1)
                s += __shfl_down_sync(0xffffffffu, s, off);
            if (lane == 0) {
                if (wid == 0) out[b] = s + bc[0];
                else          out[NPROP + b * 6 + (wid - 1)] = s + br[wid - 1];
            }
        }
    }
}

extern "C" void kernel_launch(void* const* d_in, const int* in_sizes, int n_in,
                              void* d_out, int out_size)
{
    const float* points    = (const float*)d_in[0];
    const int*   counts    = (const int*)  d_in[1];
    const float* proposals = (const float*)d_in[2];
    const float* W1 = (const float*)d_in[3];
    const float* b1 = (const float*)d_in[4];
    const float* W2 = (const float*)d_in[5];
    const float* b2 = (const float*)d_in[6];
    const float* W3 = (const float*)d_in[7];
    const float* b3 = (const float*)d_in[8];
    const float* Wc = (const float*)d_in[9];
    const float* bc = (const float*)d_in[10];
    const float* Wr = (const float*)d_in[11];
    const float* br = (const float*)d_in[12];
    float* out = (float*)d_out;

    cudaFuncSetAttribute(refine_head_kernel,
                         cudaFuncAttributeMaxDynamicSharedMemorySize, SMEM_BYTES);
    refine_head_kernel<<<NPROP, 256, SMEM_BYTES>>>(
        points, counts, proposals, W1, b1, W2, b2, W3, b3, Wc, bc, Wr, br, out);
}

// round 13
// speedup vs baseline: 1.0375x; 1.0375x over previous
#include <cuda_runtime.h>
#include <cstdint>

#define NPROP   2048
#define MAXN    256
#define D1      64
#define D2      128
#define D3      256
#define MIN_PTS 4
#define EPS     1e-6f

// ---- smem layout (float offsets) ----
// Interleaved-pair layout: k-rows (k, k+4) stored adjacent so a B-fragment
// (b0=row k, b1=row k+4) is ONE float2 LDS.  pair-row g = (k>>3)*4 + (k&3),
// half = (k>>2)&1, addr = g*PSTRIDE + col*2 + half.
// PSTRIDE = 2*256 + 8  ->  stride mod 32 banks = 8: quad pattern (tid4,gid)
// hits banks tid4*8 + gid*2 + {0,1} = all 32 distinct per half-warp.
#define PSTRIDE  520
#define OFF_FE   0                              // 256 pooled feats
#define OFF_H1T  256                            // 32 pair-rows (k=64)
#define OFF_H2T  (256 + 32 * PSTRIDE)           // 64 pair-rows (k=128)
#define SMEM_FLOATS (OFF_H2T + 64 * PSTRIDE)    // 50176
#define SMEM_BYTES  (SMEM_FLOATS * 4)           // 200,704 B (1 CTA/SM)

// round fp32 -> nearest tf32-representable value (bits / float)
__device__ __forceinline__ uint32_t f32_to_tf32_bits(float x) {
    uint32_t r;
    asm("cvt.rna.tf32.f32 %0, %1;" : "=r"(r) : "f"(x));
    return r;
}
__device__ __forceinline__ float f32_to_tf32_f(float x) {
    return __uint_as_float(f32_to_tf32_bits(x));
}

// D(16x8) += A(16x8,row) * B(8x8,col), tf32 in, f32 accum (sm_80+ baseline PTX).
#define MMA_TF32(c, a, b0, b1) \
    asm volatile("mma.sync.aligned.m16n8k8.row.col.f32.tf32.tf32.f32 " \
        "{%0,%1,%2,%3}, {%4,%5,%6,%7}, {%8,%9}, {%0,%1,%2,%3};" \
        : "+f"((c)[0]), "+f"((c)[1]), "+f"((c)[2]), "+f"((c)[3]) \
        : "r"((a)[0]), "r"((a)[1]), "r"((a)[2]), "r"((a)[3]), \
          "r"(b0), "r"(b1))

__global__ __launch_bounds__(256, 1)
void refine_head_kernel(const float* __restrict__ points,
                        const int*   __restrict__ counts,
                        const float* __restrict__ proposals,
                        const float* __restrict__ W1, const float* __restrict__ b1,
                        const float* __restrict__ W2, const float* __restrict__ b2,
                        const float* __restrict__ W3, const float* __restrict__ b3,
                        const float* __restrict__ Wc, const float* __restrict__ bc,
                        const float* __restrict__ Wr, const float* __restrict__ br,
                        float* __restrict__ out)
{
    extern __shared__ float sm[];
    const int b    = blockIdx.x;
    const int tid  = threadIdx.x;
    const int wid  = tid >> 5;
    const int lane = tid & 31;
    const int tid4 = lane & 3;
    const int gid  = lane >> 2;
    const int n    = counts[b];

    // Invalid proposal: outputs are pure biases (uniform early-out).
    if (n < MIN_PTS) {
        if (tid == 0) out[b] = bc[0];
        if (tid < 6)  out[NPROP + b * 6 + tid] = br[tid];
        return;
    }

    // ---- Hoisted: W3 A-fragments (L2-hot LDG + cvt) load while phase 0 runs. ----
    const int chb3 = wid * 32;
    uint32_t A3[16][2][4];
    #pragma unroll
    for (int s = 0; s < 16; s++) {
        const int j0 = s * 8 + tid4;
        #pragma unroll
        for (int mt = 0; mt < 2; mt++) {
            const int ch = chb3 + mt * 16 + gid;
            A3[s][mt][0] = f32_to_tf32_bits(__ldg(W3 + j0 * D3 + ch));
            A3[s][mt][1] = f32_to_tf32_bits(__ldg(W3 + j0 * D3 + ch + 8));
            A3[s][mt][2] = f32_to_tf32_bits(__ldg(W3 + (j0 + 4) * D3 + ch));
            A3[s][mt][3] = f32_to_tf32_bits(__ldg(W3 + (j0 + 4) * D3 + ch + 8));
        }
    }

    // ---- Phase 0: thread = point (only the first n unique points matter —
    // the reference's arange(256)%n gather merely duplicates points and
    // max-pool is duplicate-invariant). Layer 1 -> h1t pairs, tf32. ----
    if (tid < n) {
        const float* pp = points + ((long)b * MAXN + tid) * 3;
        const float* pr = proposals + b * 6;
        const float c0 = (pp[0] - pr[0]) / (fabsf(pr[3]) + EPS);
        const float c1 = (pp[1] - pr[1]) / (fabsf(pr[4]) + EPS);
        const float c2 = (pp[2] - pr[2]) / (fabsf(pr[5]) + EPS);

        #pragma unroll
        for (int s = 0; s < 8; s++) {
            float h[8];
            #pragma unroll
            for (int hf = 0; hf < 2; hf++) {
                float4 a = __ldg((const float4*)(W1)       + s * 2 + hf);
                float4 d = __ldg((const float4*)(W1 + 64)  + s * 2 + hf);
                float4 e = __ldg((const float4*)(W1 + 128) + s * 2 + hf);
                float4 f = __ldg((const float4*)(b1)       + s * 2 + hf);
                h[hf*4+0] = fmaxf(fmaf(c0, a.x, fmaf(c1, d.x, fmaf(c2, e.x, f.x))), 0.f);
                h[hf*4+1] = fmaxf(fmaf(c0, a.y, fmaf(c1, d.y, fmaf(c2, e.y, f.y))), 0.f);
                h[hf*4+2] = fmaxf(fmaf(c0, a.z, fmaf(c1, d.z, fmaf(c2, e.z, f.z))), 0.f);
                h[hf*4+3] = fmaxf(fmaf(c0, a.w, fmaf(c1, d.w, fmaf(c2, e.w, f.w))), 0.f);
            }
            // store pairs (k = s*8+t, k+4) as one float2
            #pragma unroll
            for (int t = 0; t < 4; t++) {
                float2 v;
                v.x = f32_to_tf32_f(h[t]);
                v.y = f32_to_tf32_f(h[t + 4]);
                *(float2*)&sm[OFF_H1T + (s * 4 + t) * PSTRIDE + tid * 2] = v;
            }
        }
    }
    __syncthreads();

    const int c16 = (n + 15) >> 4;

    // ---- Layer 2 on tensor cores: D[ch][pt] = W2T @ h1t.  Warp w owns the
    // m16 channel tile [w*16, w*16+16).  Output goes to h2t pair layout. ----
    {
        const int chb = wid * 16;

        uint32_t A2[8][4];
        #pragma unroll
        for (int s = 0; s < 8; s++) {
            const int j0 = s * 8 + tid4;
            A2[s][0] = f32_to_tf32_bits(__ldg(W2 + j0 * D2 + chb + gid));
            A2[s][1] = f32_to_tf32_bits(__ldg(W2 + j0 * D2 + chb + gid + 8));
            A2[s][2] = f32_to_tf32_bits(__ldg(W2 + (j0 + 4) * D2 + chb + gid));
            A2[s][3] = f32_to_tf32_bits(__ldg(W2 + (j0 + 4) * D2 + chb + gid + 8));
        }
        const float b2v0 = __ldg(b2 + chb + gid);
        const float b2v1 = __ldg(b2 + chb + gid + 8);

        // epilogue store geometry (pair layout) for channels j0=chb+gid, j1=j0+8
        const int g0 = 8 * wid + (gid & 3);
        const int g1 = g0 + 4;
        const int h0 = (gid >> 2) & 1;

        for (int ck = 0; ck < c16; ck++) {
            const int colb = ck * 16;
            float c2f[2][4];
            #pragma unroll
            for (int nt = 0; nt < 2; nt++)
                #pragma unroll
                for (int q = 0; q < 4; q++) c2f[nt][q] = 0.f;

            #pragma unroll
            for (int s = 0; s < 8; s++) {
                const float* base = &sm[OFF_H1T + (s * 4 + tid4) * PSTRIDE];
                float2 p0 = *(const float2*)&base[(colb + gid) * 2];
                float2 p1 = *(const float2*)&base[(colb + 8 + gid) * 2];
                MMA_TF32(c2f[0], A2[s], __float_as_uint(p0.x), __float_as_uint(p0.y));
                MMA_TF32(c2f[1], A2[s], __float_as_uint(p1.x), __float_as_uint(p1.y));
            }

            // epilogue: relu + bias, tf32-round, store into h2t pair layout
            #pragma unroll
            for (int nt = 0; nt < 2; nt++) {
                const int col0 = colb + nt * 8 + 2 * tid4;
                sm[OFF_H2T + g0 * PSTRIDE + col0 * 2 + h0] =
                    f32_to_tf32_f(fmaxf(c2f[nt][0] + b2v0, 0.f));
                sm[OFF_H2T + g0 * PSTRIDE + (col0 + 1) * 2 + h0] =
                    f32_to_tf32_f(fmaxf(c2f[nt][1] + b2v0, 0.f));
                sm[OFF_H2T + g1 * PSTRIDE + col0 * 2 + h0] =
                    f32_to_tf32_f(fmaxf(c2f[nt][2] + b2v1, 0.f));
                sm[OFF_H2T + g1 * PSTRIDE + (col0 + 1) * 2 + h0] =
                    f32_to_tf32_f(fmaxf(c2f[nt][3] + b2v1, 0.f));
            }
        }
    }
    __syncthreads();

    // ---- Layer 3 + max-pool on tensor cores.  Warp w owns channels
    // [w*32, w*32+32): 2 m16 tiles sharing each B-fragment (A3 preloaded). ----
    float mx[4] = {-3.402823466e38f, -3.402823466e38f,
                   -3.402823466e38f, -3.402823466e38f};   // [mt*2 + rowhalf]
    {
        for (int ck = 0; ck < c16; ck++) {
            const int colb = ck * 16;
            float c[2][2][4];
            #pragma unroll
            for (int mt = 0; mt < 2; mt++)
                #pragma unroll
                for (int nt = 0; nt < 2; nt++)
                    #pragma unroll
                    for (int q = 0; q < 4; q++) c[mt][nt][q] = 0.f;

            #pragma unroll
            for (int s = 0; s < 16; s++) {
                const float* base = &sm[OFF_H2T + (s * 4 + tid4) * PSTRIDE];
                float2 p0 = *(const float2*)&base[(colb + gid) * 2];
                float2 p1 = *(const float2*)&base[(colb + 8 + gid) * 2];
                const uint32_t b00 = __float_as_uint(p0.x), b01 = __float_as_uint(p0.y);
                const uint32_t b10 = __float_as_uint(p1.x), b11 = __float_as_uint(p1.y);
                MMA_TF32(c[0][0], A3[s][0], b00, b01);
                MMA_TF32(c[1][0], A3[s][1], b00, b01);
                MMA_TF32(c[0][1], A3[s][0], b10, b11);
                MMA_TF32(c[1][1], A3[s][1], b10, b11);
            }

            // fold into running per-row max (mask cols >= n)
            #pragma unroll
            for (int mt = 0; mt < 2; mt++) {
                #pragma unroll
                for (int nt = 0; nt < 2; nt++) {
                    const int col0 = colb + nt * 8 + 2 * tid4;
                    if (col0 < n) {
                        mx[mt*2+0] = fmaxf(mx[mt*2+0], c[mt][nt][0]);
                        mx[mt*2+1] = fmaxf(mx[mt*2+1], c[mt][nt][2]);
                    }
                    if (col0 + 1 < n) {
                        mx[mt*2+0] = fmaxf(mx[mt*2+0], c[mt][nt][1]);
                        mx[mt*2+1] = fmaxf(mx[mt*2+1], c[mt][nt][3]);
                    }
                }
            }
        }
    }

    // ---- Pool finish: quad-lane max union, + b3 -> feats in smem ----
    {
        #pragma unroll
        for (int o = 1; o < 4; o <<= 1) {
            #pragma unroll
            for (int q = 0; q < 4; q++)
                mx[q] = fmaxf(mx[q], __shfl_xor_sync(0xffffffffu, mx[q], o));
        }
        if (tid4 == 0) {
            #pragma unroll
            for (int mt = 0; mt < 2; mt++)
                #pragma unroll
                for (int rh = 0; rh < 2; rh++) {
                    const int ch = chb3 + mt * 16 + rh * 8 + gid;
                    sm[OFF_FE + ch] = mx[mt*2+rh] + __ldg(b3 + ch);
                }
        }
    }
    __syncthreads();

    // ---- Heads: 7 warps, each one dot(feats, column) + bias ----
    {
        if (wid < 7) {
            float s = 0.f;
            if (wid == 0) {
                #pragma unroll
                for (int k = lane; k < D3; k += 32) s += sm[OFF_FE + k] * __ldg(Wc + k);
            } else {
                const int r = wid - 1;
                #pragma unroll
                for (int k = lane; k < D3; k += 32) s += sm[OFF_FE + k] * __ldg(Wr + k * 6 + r);
            }
            #pragma unroll
            for (int off = 16; off > 0; off >>= 1)
                s += __shfl_down_sync(0xffffffffu, s, off);
            if (lane == 0) {
                if (wid == 0) out[b] = s + bc[0];
                else          out[NPROP + b * 6 + (wid - 1)] = s + br[wid - 1];
            }
        }
    }
}

extern "C" void kernel_launch(void* const* d_in, const int* in_sizes, int n_in,
                              void* d_out, int out_size)
{
    const float* points    = (const float*)d_in[0];
    const int*   counts    = (const int*)  d_in[1];
    const float* proposals = (const float*)d_in[2];
    const float* W1 = (const float*)d_in[3];
    const float* b1 = (const float*)d_in[4];
    const float* W2 = (const float*)d_in[5];
    const float* b2 = (const float*)d_in[6];
    const float* W3 = (const float*)d_in[7];
    const float* b3 = (const float*)d_in[8];
    const float* Wc = (const float*)d_in[9];
    const float* bc = (const float*)d_in[10];
    const float* Wr = (const float*)d_in[11];
    const float* br = (const float*)d_in[12];
    float* out = (float*)d_out;

    cudaFuncSetAttribute(refine_head_kernel,
                         cudaFuncAttributeMaxDynamicSharedMemorySize, SMEM_BYTES);
    refine_head_kernel<<<NPROP, 256, SMEM_BYTES>>>(
        points, counts, proposals, W1, b1, W2, b2, W3, b3, Wc, bc, Wr, br, out);
}